// round 2
// baseline (speedup 1.0000x reference)
#include <cuda_runtime.h>
#include <cuda_pipeline.h>
#include <cstdint>

#define TT 512
#define BB_ 256
#define DIN 64
#define HH 256
#define GG 1024   // 4*H
#define DOUT 8

#define NB 4          // batches per CTA
#define NC (BB_/NB)   // 64 CTAs
#define CHUNK_K 8
#define NBUF 4
#define NCHUNK (HH/CHUNK_K)   // 32

// ---------------- device scratch (static, allowed) ----------------
__device__ float g_Xp[(size_t)BB_*TT*GG];   // [b][t][rr] fp32, 512MB
__device__ float g_Wt[(size_t)HH*GG];       // [k][rr] transposed+reordered W_hh (1MB)
__device__ float g_Wr_ih[(size_t)GG*DIN];   // reordered rows of W_ih
__device__ float g_br[GG];                  // reordered bias

// rr = 4*j + g  (g in order i,f,g,o), orig row = g*H + j
__global__ void reorder_whh_kernel(const float* __restrict__ W_hh) {
    int k = blockIdx.x;  // 0..255
    for (int rr = threadIdx.x; rr < GG; rr += blockDim.x) {
        int jj = rr >> 2, g = rr & 3;
        g_Wt[(size_t)k * GG + rr] = W_hh[(size_t)(g * HH + jj) * HH + k];
    }
}

__global__ void reorder_wih_kernel(const float* __restrict__ W_ih,
                                   const float* __restrict__ bias) {
    int rr = blockIdx.x;
    int jj = rr >> 2, g = rr & 3;
    int orig = g * HH + jj;
    if (threadIdx.x < DIN)
        g_Wr_ih[(size_t)rr * DIN + threadIdx.x] = W_ih[(size_t)orig * DIN + threadIdx.x];
    if (threadIdx.x == 0) g_br[rr] = bias[orig];
}

// ---------------- input projection GEMM ----------------
// Xp[m][rr] = sum_k x[m][k] * Wr_ih[rr][k] + br[rr],  m = b*T + t
// tile 64m x 64n, K=64 full. 256 threads, 4x4 outputs per thread.
__global__ void __launch_bounds__(256) xproj_kernel(const float* __restrict__ x) {
    __shared__ float As[DIN][68];   // [k][m]
    __shared__ float Bs[DIN][68];   // [k][n]
    int m0 = blockIdx.x * 64, n0 = blockIdx.y * 64;
    int tid = threadIdx.x;

    for (int i = tid; i < 1024; i += 256) {
        int r  = i >> 4;       // row 0..63
        int kq = i & 15;       // float4 index within 64 k
        float4 v = ((const float4*)(x + (size_t)(m0 + r) * DIN))[kq];
        As[kq*4+0][r] = v.x; As[kq*4+1][r] = v.y; As[kq*4+2][r] = v.z; As[kq*4+3][r] = v.w;
        float4 w = ((const float4*)(g_Wr_ih + (size_t)(n0 + r) * DIN))[kq];
        Bs[kq*4+0][r] = w.x; Bs[kq*4+1][r] = w.y; Bs[kq*4+2][r] = w.z; Bs[kq*4+3][r] = w.w;
    }
    __syncthreads();

    int tm = (tid >> 4) << 2;
    int tn = (tid & 15) << 2;
    float acc[4][4] = {};
    #pragma unroll 8
    for (int k = 0; k < DIN; k++) {
        float a[4], b[4];
        *(float4*)a = *(const float4*)&As[k][tm];
        *(float4*)b = *(const float4*)&Bs[k][tn];
        #pragma unroll
        for (int i = 0; i < 4; i++)
            #pragma unroll
            for (int jj = 0; jj < 4; jj++)
                acc[i][jj] += a[i] * b[jj];
    }
    float4 bias = *(const float4*)(g_br + n0 + tn);
    #pragma unroll
    for (int i = 0; i < 4; i++) {
        float4 r;
        r.x = acc[i][0] + bias.x; r.y = acc[i][1] + bias.y;
        r.z = acc[i][2] + bias.z; r.w = acc[i][3] + bias.w;
        *(float4*)(g_Xp + (size_t)(m0 + tm + i) * GG + n0 + tn) = r;
    }
}

// ---------------- LSTM recurrence ----------------
#define FMA2(acc, a, b) asm("fma.rn.f32x2 %0, %1, %2, %0;" : "+l"(acc) : "l"(a), "l"(b))

__device__ __forceinline__ float lof(unsigned long long v) { return __uint_as_float((unsigned)v); }
__device__ __forceinline__ float hif(unsigned long long v) { return __uint_as_float((unsigned)(v >> 32)); }
__device__ __forceinline__ unsigned long long dupf(float f) {
    unsigned u = __float_as_uint(f);
    return (unsigned long long)u | ((unsigned long long)u << 32);
}
__device__ __forceinline__ float sigf(float x)  { return 1.f / (1.f + __expf(-x)); }
__device__ __forceinline__ float tanhf_fast(float x) { return 2.f / (1.f + __expf(-2.f * x)) - 1.f; }

__device__ __forceinline__ void stage_chunk(float* w_buf, int buf, int k0, int tid) {
    const float4* src = (const float4*)(g_Wt + (size_t)k0 * GG);
    float4* dst = (float4*)(w_buf + (size_t)buf * CHUNK_K * GG);
    #pragma unroll
    for (int i = 0; i < (CHUNK_K * GG / 4) / 256; i++)   // 8 x 16B per thread
        __pipeline_memcpy_async(dst + tid + i * 256, src + tid + i * 256, 16);
    __pipeline_commit();
}

__global__ void __launch_bounds__(256, 1) lstm_kernel(const float* __restrict__ h0,
                                                      const float* __restrict__ c0,
                                                      float* __restrict__ out) {
    extern __shared__ char smem[];
    float* w_buf = (float*)smem;                                           // [NBUF][CHUNK_K][GG]
    unsigned long long* sh_h =
        (unsigned long long*)(smem + (size_t)NBUF * CHUNK_K * GG * 4);     // [2][HH][NB], dup'd

    const int tid = threadIdx.x;
    const int j   = tid;                 // h index 0..255
    const int b0  = blockIdx.x * NB;

    float c[NB], hlast[NB];
    #pragma unroll
    for (int bb = 0; bb < NB; bb++) {
        c[bb] = c0[(size_t)(b0 + bb) * HH + j];
        float hv = h0[(size_t)(b0 + bb) * HH + j];
        hlast[bb] = hv;
        sh_h[(size_t)j * NB + bb] = dupf(hv);
    }

    stage_chunk(w_buf, 0, 0, tid);
    stage_chunk(w_buf, 1, CHUNK_K, tid);
    stage_chunk(w_buf, 2, 2 * CHUNK_K, tid);
    __syncthreads();

    int cur = 0;
    for (int t = 0; t < TT; t++) {
        unsigned long long acc[2][NB];
        #pragma unroll
        for (int bb = 0; bb < NB; bb++) {
            ulonglong2 xv = *(const ulonglong2*)(g_Xp + ((size_t)(b0 + bb) * TT + t) * GG + 4 * j);
            acc[0][bb] = xv.x;   // gates (i,f)
            acc[1][bb] = xv.y;   // gates (g,o)
        }

        #pragma unroll 1
        for (int ch = 0; ch < NCHUNK; ch++) {
            __pipeline_wait_prior(2);
            __syncthreads();
            int nc = ch + 3; if (nc >= NCHUNK) nc -= NCHUNK;
            stage_chunk(w_buf, (ch + 3) & 3, nc * CHUNK_K, tid);

            const float* wb = w_buf + (size_t)(ch & 3) * CHUNK_K * GG;
            const unsigned long long* hb =
                sh_h + (size_t)cur * HH * NB + (size_t)ch * CHUNK_K * NB;
            #pragma unroll
            for (int kk = 0; kk < CHUNK_K; kk++) {
                ulonglong2 w    = *(const ulonglong2*)(wb + (size_t)kk * GG + 4 * j);
                ulonglong2 hd01 = *(const ulonglong2*)(hb + kk * NB);
                ulonglong2 hd23 = *(const ulonglong2*)(hb + kk * NB + 2);
                FMA2(acc[0][0], w.x, hd01.x); FMA2(acc[1][0], w.y, hd01.x);
                FMA2(acc[0][1], w.x, hd01.y); FMA2(acc[1][1], w.y, hd01.y);
                FMA2(acc[0][2], w.x, hd23.x); FMA2(acc[1][2], w.y, hd23.x);
                FMA2(acc[0][3], w.x, hd23.y); FMA2(acc[1][3], w.y, hd23.y);
            }
        }

        int nxt = cur ^ 1;
        unsigned long long* hw = sh_h + (size_t)nxt * HH * NB + (size_t)j * NB;
        #pragma unroll
        for (int bb = 0; bb < NB; bb++) {
            float ip = lof(acc[0][bb]), fp = hif(acc[0][bb]);
            float gp = lof(acc[1][bb]), op = hif(acc[1][bb]);
            float ig = sigf(ip), fg = sigf(fp), og = sigf(op);
            float gg = tanhf_fast(gp);
            c[bb] = fg * c[bb] + ig * gg;
            float hn = og * tanhf_fast(c[bb]);
            hlast[bb] = hn;
            hw[bb] = dupf(hn);
        }
        cur = nxt;
        // no extra barrier: next chunk-0 __syncthreads orders these writes
    }

    // outputs: rnn_outputs @0, logits @65536, h @67584, c @133120
    #pragma unroll
    for (int bb = 0; bb < NB; bb++) {
        size_t idx = (size_t)(b0 + bb) * HH + j;
        out[idx]           = hlast[bb];
        out[67584 + idx]   = hlast[bb];
        out[133120 + idx]  = c[bb];
    }
}

// ---------------- output projection ----------------
__global__ void logits_kernel(const float* __restrict__ hbase,
                              const float* __restrict__ W_out,
                              const float* __restrict__ b_out,
                              float* __restrict__ out_logits) {
    int b = blockIdx.x;
    int d = threadIdx.x >> 5;     // 8 warps = 8 outputs
    int lane = threadIdx.x & 31;
    const float* hr = hbase + (size_t)b * HH;
    const float* wr = W_out + (size_t)d * HH;
    float s = 0.f;
    #pragma unroll
    for (int k = lane; k < HH; k += 32) s += hr[k] * wr[k];
    #pragma unroll
    for (int o = 16; o; o >>= 1) s += __shfl_down_sync(0xffffffffu, s, o);
    if (lane == 0) out_logits[b * DOUT + d] = s + b_out[d];
}

// ---------------- launch ----------------
extern "C" void kernel_launch(void* const* d_in, const int* in_sizes, int n_in,
                              void* d_out, int out_size) {
    const float* x     = (const float*)d_in[0];
    const float* h0    = (const float*)d_in[1];
    const float* c0    = (const float*)d_in[2];
    const float* W_ih  = (const float*)d_in[3];
    const float* W_hh  = (const float*)d_in[4];
    const float* bias  = (const float*)d_in[5];
    const float* W_out = (const float*)d_in[6];
    const float* b_out = (const float*)d_in[7];
    float* out = (float*)d_out;

    reorder_whh_kernel<<<HH, 256>>>(W_hh);
    reorder_wih_kernel<<<GG, 64>>>(W_ih, bias);

    xproj_kernel<<<dim3((BB_ * TT) / 64, GG / 64), 256>>>(x);

    size_t smem_bytes = (size_t)NBUF * CHUNK_K * GG * 4 + (size_t)2 * HH * NB * 8; // 147456
    cudaFuncSetAttribute(lstm_kernel, cudaFuncAttributeMaxDynamicSharedMemorySize,
                         (int)smem_bytes);
    lstm_kernel<<<NC, 256, smem_bytes>>>(h0, c0, out);

    logits_kernel<<<BB_, 256>>>(out, W_out, b_out, out + 65536);
}